// round 9
// baseline (speedup 1.0000x reference)
#include <cuda_runtime.h>
#include <cuda_fp16.h>
#include <math.h>

// Problem constants (fixed by the dataset)
#define N_MAX 100000
#define E_MAX 3200000
#define CH 48            // K*H = 3*16
#define ZSTRIDE 32       // half2 words per node row (24 used, 128B-aligned rows)
#define SCAN_CHUNK 1024
#define SCAN_NB ((N_MAX + SCAN_CHUNK - 1) / SCAN_CHUNK)   // 98

// ---------------- persistent device scratch ----------------
__device__ float   g_deg[N_MAX];
__device__ float2  g_xd[N_MAX];          // packed {x, dinv}
__device__ int     g_cnt[N_MAX];
__device__ int     g_colptr[N_MAX + 1];
__device__ int     g_epos[E_MAX];        // per-edge rank within its target bucket
__device__ int     g_bsum[SCAN_NB];
__device__ uint2   g_csr[E_MAX];         // {src, attr-bits} then {src, norm-bits}
__device__ __align__(16) __half2 g_z2[(size_t)N_MAX * ZSTRIDE]; // padded state rows
__device__ float   g_out[(size_t)N_MAX * CH]; // post-epilogue out (fp32)
__device__ float4  g_s[2][N_MAX];        // conv2 state ping/pong
__device__ float4  g_r2[N_MAX];          // conv2 root+bias per stack
__device__ float   g_bnsum[16];
__device__ float   g_bnsq[16];

// ---------------- preprocessing ----------------
__global__ void k_zero(int n) {
    int i = blockIdx.x * blockDim.x + threadIdx.x;
    if (i < n) { g_deg[i] = 0.f; g_cnt[i] = 0; }
    if (i < 16) { g_bnsum[i] = 0.f; g_bnsq[i] = 0.f; }
}

// edge_index is int32. Record each edge's bucket rank from the cnt atomic.
__global__ void k_pre(const int* __restrict__ ei, const float* __restrict__ attr, int E, int n) {
    int e = blockIdx.x * blockDim.x + threadIdx.x;
    if (e >= E) return;
    int c = ei[E + e];
    c = min(max(c, 0), n - 1);
    atomicAdd(&g_deg[c], attr[e]);
    g_epos[e] = atomicAdd(&g_cnt[c], 1);
}

// fused: {x, dinv} pack for this block's 1024 nodes + block sum of cnt
__global__ void k_dinv_blocksum(const float* __restrict__ x, int n) {
    __shared__ int sh[256];
    int base = blockIdx.x * SCAN_CHUNK;
    int tid = threadIdx.x;
    int s = 0;
    #pragma unroll
    for (int j = 0; j < 4; j++) {
        int i = base + tid * 4 + j;
        if (i < n) {
            float d = g_deg[i];
            float dv = (d > 0.f) ? rsqrtf(fmaxf(d, 1e-12f)) : 0.f;
            g_xd[i] = make_float2(x[i], dv);
            s += g_cnt[i];
        }
    }
    sh[tid] = s;
    __syncthreads();
    for (int off = 128; off; off >>= 1) {
        if (tid < off) sh[tid] += sh[tid + off];
        __syncthreads();
    }
    if (tid == 0) g_bsum[blockIdx.x] = sh[0];
}

// fillptr with inline prefix of block sums
__global__ void k_fillptr(int n, int total) {
    __shared__ int sh[256];
    __shared__ int s_boff;
    int base = blockIdx.x * SCAN_CHUNK;
    int tid = threadIdx.x;
    if (tid < 32) {
        int acc = 0;
        for (int i = tid; i < blockIdx.x; i += 32) acc += g_bsum[i];
        #pragma unroll
        for (int o = 16; o; o >>= 1) acc += __shfl_xor_sync(0xffffffffu, acc, o);
        if (tid == 0) s_boff = acc;
    }
    int c[4];
    int s = 0;
    #pragma unroll
    for (int j = 0; j < 4; j++) {
        int i = base + tid * 4 + j;
        c[j] = (i < n) ? g_cnt[i] : 0;
        s += c[j];
    }
    sh[tid] = s;
    __syncthreads();
    for (int off = 1; off < 256; off <<= 1) {
        int v = (tid >= off) ? sh[tid - off] : 0;
        __syncthreads();
        sh[tid] += v;
        __syncthreads();
    }
    int run = s_boff + ((tid > 0) ? sh[tid - 1] : 0);
    #pragma unroll
    for (int j = 0; j < 4; j++) {
        int i = base + tid * 4 + j;
        if (i < n) { g_colptr[i] = run; run += c[j]; }
    }
    if (blockIdx.x == 0 && tid == 0) g_colptr[n] = total;
}

// scatter {src, attr}: no dinv gathers; norm computed later in k_prop1i
__global__ void k_scatter(const int* __restrict__ ei, const float* __restrict__ attr, int E, int n) {
    int e = blockIdx.x * blockDim.x + threadIdx.x;
    if (e >= E) return;
    int r = ei[e];
    int c = ei[E + e];
    r = min(max(r, 0), n - 1);
    c = min(max(c, 0), n - 1);
    g_csr[g_colptr[c] + g_epos[e]] = make_uint2((unsigned)r, __float_as_uint(attr[e]));
}

// ---------------- conv1 layer 0, fused ----------------
// per node: finalize norms in CSR, y = A_hat x, out1 = relu(y*wi + x*wr + b), z = out1 @ W
__global__ void k_prop1i(const float* __restrict__ wi, const float* __restrict__ W,
                         const float* __restrict__ wr, const float* __restrict__ b, int n) {
    __shared__ float s_wi[48], s_wr[48], s_b[48], s_W[768];
    int tid = threadIdx.x;
    if (tid < 48) { s_wi[tid] = wi[tid]; s_wr[tid] = wr[tid]; s_b[tid] = b[tid]; }
    for (int i = tid; i < 768; i += 256) s_W[i] = W[i];
    __syncthreads();

    int w = blockIdx.x * 8 + (tid >> 5);
    if (w >= n) return;
    int lane = tid & 31;
    float2 xdw = g_xd[w];
    float dinv_w = xdw.y, xv = xdw.x;
    int beg = g_colptr[w], end = g_colptr[w + 1];
    float acc = 0.f;
    for (int i = beg + lane; i < end; i += 32) {
        uint2 e = g_csr[i];
        float2 xd = g_xd[e.x];
        float nm = xd.y * __uint_as_float(e.y) * dinv_w;
        g_csr[i] = make_uint2(e.x, __float_as_uint(nm));
        acc += xd.x * nm;
    }
    #pragma unroll
    for (int o = 16; o; o >>= 1) acc += __shfl_xor_sync(0xffffffffu, acc, o);
    float yv = acc;   // all lanes have y

    if (lane < 24) {
        int k = lane >> 3;      // stack
        int j = lane & 7;       // half2 word within stack
        const float* wik = s_wi + k * 16;
        const float* wrk = s_wr + k * 16;
        const float* bk  = s_b  + k * 16;
        const float* Wk  = s_W  + k * 256;
        float z0 = 0.f, z1 = 0.f;
        #pragma unroll
        for (int hi = 0; hi < 16; hi++) {
            float o = fmaxf(yv * wik[hi] + xv * wrk[hi] + bk[hi], 0.f);
            z0 += o * Wk[hi * 16 + 2 * j];
            z1 += o * Wk[hi * 16 + 2 * j + 1];
        }
        g_z2[(size_t)w * ZSTRIDE + k * 8 + j] = __floats2half2_rn(z0, z1);
    }
}

// hot kernel: out = relu(A_hat @ z + x*w_root + b); optionally fused z' = out @ W
// warp = 4 edge-slots x 6 chan-slots (24 active lanes); pad words never fetched.
__global__ void k_prop48(const float* __restrict__ wr, const float* __restrict__ b,
                         const float* __restrict__ W, int doTrans, int n) {
    __shared__ float s_out[8][CH];   // per-warp out vector
    __shared__ float s_W[768];       // 3 stacks x 16 x 16
    int tid = threadIdx.x;
    if (doTrans) {
        for (int i = tid; i < 768; i += 256) s_W[i] = W[i];
    }
    __syncthreads();

    int warpid = tid >> 5;
    int w = blockIdx.x * 8 + warpid;
    if (w >= n) return;
    int lane = tid & 31;
    bool act = lane < 24;
    int es = lane / 6;            // edge slot 0..3 (active lanes)
    int cs = lane - es * 6;       // chan slot 0..5
    int beg = g_colptr[w], end = g_colptr[w + 1];
    float accA[8] = {0.f, 0.f, 0.f, 0.f, 0.f, 0.f, 0.f, 0.f};
    float accB[8] = {0.f, 0.f, 0.f, 0.f, 0.f, 0.f, 0.f, 0.f};

    if (beg < end) {
        int last = end - 1;
        uint2 e0 = make_uint2(0u, 0u), e1 = make_uint2(0u, 0u);
        bool ok0 = false, ok1 = false;
        if (act) {
            e0 = g_csr[min(beg + es, last)];
            e1 = g_csr[min(beg + es + 4, last)];
            ok0 = beg + es < end; ok1 = beg + es + 4 < end;
        }
        for (int i = beg; i < end; i += 8) {
            int4 v0 = make_int4(0, 0, 0, 0), v1 = make_int4(0, 0, 0, 0);
            float n0 = 0.f, n1 = 0.f;
            if (act) {
                v0 = *((const int4*)(g_z2 + (size_t)e0.x * ZSTRIDE) + cs);
                v1 = *((const int4*)(g_z2 + (size_t)e1.x * ZSTRIDE) + cs);
                n0 = ok0 ? __uint_as_float(e0.y) : 0.f;
                n1 = ok1 ? __uint_as_float(e1.y) : 0.f;
                int ni = i + 8;
                if (ni < end) {
                    e0 = g_csr[min(ni + es, last)];
                    e1 = g_csr[min(ni + es + 4, last)];
                    ok0 = ni + es < end; ok1 = ni + es + 4 < end;
                }
            }
            {
                float2 f0 = __half22float2(*(__half2*)&v0.x);
                float2 f1 = __half22float2(*(__half2*)&v0.y);
                float2 f2 = __half22float2(*(__half2*)&v0.z);
                float2 f3 = __half22float2(*(__half2*)&v0.w);
                accA[0] += f0.x * n0; accA[1] += f0.y * n0;
                accA[2] += f1.x * n0; accA[3] += f1.y * n0;
                accA[4] += f2.x * n0; accA[5] += f2.y * n0;
                accA[6] += f3.x * n0; accA[7] += f3.y * n0;
            }
            {
                float2 f0 = __half22float2(*(__half2*)&v1.x);
                float2 f1 = __half22float2(*(__half2*)&v1.y);
                float2 f2 = __half22float2(*(__half2*)&v1.z);
                float2 f3 = __half22float2(*(__half2*)&v1.w);
                accB[0] += f0.x * n1; accB[1] += f0.y * n1;
                accB[2] += f1.x * n1; accB[3] += f1.y * n1;
                accB[4] += f2.x * n1; accB[5] += f2.y * n1;
                accB[6] += f3.x * n1; accB[7] += f3.y * n1;
            }
        }
    }
    // fold 4 edge slots: lanes {cs, cs+6, cs+12, cs+18} -> lane cs
    #pragma unroll
    for (int c = 0; c < 8; c++) {
        float a = accA[c] + accB[c];
        a += __shfl_down_sync(0xffffffffu, a, 12);
        a += __shfl_down_sync(0xffffffffu, a, 6);
        accA[c] = a;
    }
    if (lane < 6) {
        float xv = g_xd[w].x;
        int c0 = lane * 8;
        float o[8];
        #pragma unroll
        for (int c = 0; c < 8; c++) {
            o[c] = fmaxf(accA[c] + xv * wr[c0 + c] + b[c0 + c], 0.f);
            s_out[warpid][c0 + c] = o[c];
        }
        float4* op = (float4*)(g_out + (size_t)w * CH + c0);
        op[0] = make_float4(o[0], o[1], o[2], o[3]);
        op[1] = make_float4(o[4], o[5], o[6], o[7]);
    }
    if (doTrans) {
        __syncwarp();
        if (lane < 24) {
            int k = lane >> 3;
            int j = lane & 7;
            const float* ov = s_out[warpid] + k * 16;
            const float* Wk = s_W + k * 256;
            float z0 = 0.f, z1 = 0.f;
            #pragma unroll
            for (int hi = 0; hi < 16; hi++) {
                z0 += ov[hi] * Wk[hi * 16 + 2 * j];
                z1 += ov[hi] * Wk[hi * 16 + 2 * j + 1];
            }
            g_z2[(size_t)w * ZSTRIDE + k * 8 + j] = __floats2half2_rn(z0, z1);
        }
    }
}

// ---------------- batchnorm + conv2 ----------------
__global__ void k_bnstats(int n) {
    int tid = blockIdx.x * blockDim.x + threadIdx.x;
    int stride = gridDim.x * blockDim.x;
    float s = 0.f, q = 0.f;
    for (int base = tid; base < n * 16; base += stride) {
        int node = base >> 4;
        int c = base & 15;
        const float* op = g_out + (size_t)node * CH;
        float h = (op[c] + op[16 + c] + op[32 + c]) * (1.f / 3.f);
        s += h; q += h * h;
    }
    atomicAdd(&g_bnsum[tid & 15], s);
    atomicAdd(&g_bnsq[tid & 15], q);
}

__global__ void k_conv2init(const float* __restrict__ bg, const float* __restrict__ bb,
                            const float* __restrict__ w2i, const float* __restrict__ w2r,
                            const float* __restrict__ b2, int n) {
    int node = blockIdx.x * blockDim.x + threadIdx.x;
    if (node >= n) return;
    const float* op = g_out + (size_t)node * CH;
    float invN = 1.f / (float)n;
    float s0 = 0.f, s1 = 0.f, s2 = 0.f;
    float r0 = b2[0], r1 = b2[1], r2 = b2[2];
    #pragma unroll
    for (int c = 0; c < 16; c++) {
        float h = (op[c] + op[16 + c] + op[32 + c]) * (1.f / 3.f);
        float mu = g_bnsum[c] * invN;
        float var = g_bnsq[c] * invN - mu * mu;
        float hb = (h - mu) * rsqrtf(var + 1e-5f) * bg[c] + bb[c];
        hb = fmaxf(hb, 0.f);
        s0 += hb * w2i[c];
        s1 += hb * w2i[16 + c];
        s2 += hb * w2i[32 + c];
        r0 += hb * w2r[c];
        r1 += hb * w2r[16 + c];
        r2 += hb * w2r[32 + c];
    }
    g_s[0][node] = make_float4(s0, s1, s2, 0.f);
    g_r2[node] = make_float4(r0, r1, r2, 0.f);
}

__global__ void k_prop3(int srcIdx, int useW, int finalOut,
                        const float* __restrict__ w2, float* __restrict__ dout, int n) {
    int w = (blockIdx.x * blockDim.x + threadIdx.x) >> 5;
    int lane = threadIdx.x & 31;
    if (w >= n) return;
    const float4* s = g_s[srcIdx];
    int beg = g_colptr[w], end = g_colptr[w + 1];
    float a0 = 0.f, a1 = 0.f, a2 = 0.f;
    for (int i = beg + lane; i < end; i += 32) {
        uint2 e = g_csr[i];
        float nm = __uint_as_float(e.y);
        float4 v = s[e.x];
        a0 += v.x * nm; a1 += v.y * nm; a2 += v.z * nm;
    }
    #pragma unroll
    for (int o = 16; o; o >>= 1) {
        a0 += __shfl_xor_sync(0xffffffffu, a0, o);
        a1 += __shfl_xor_sync(0xffffffffu, a1, o);
        a2 += __shfl_xor_sync(0xffffffffu, a2, o);
    }
    if (lane == 0) {
        if (useW) { a0 *= w2[0]; a1 *= w2[1]; a2 *= w2[2]; }
        float4 r = g_r2[w];
        a0 += r.x; a1 += r.y; a2 += r.z;
        if (finalOut) {
            float m = (a0 + a1 + a2) * (1.f / 3.f);
            dout[w] = 1.f / (1.f + expf(-m));
        } else {
            g_s[1 - srcIdx][w] = make_float4(a0, a1, a2, 0.f);
        }
    }
}

static inline int cdiv(int a, int b) { return (a + b - 1) / b; }

extern "C" void kernel_launch(void* const* d_in, const int* in_sizes, int n_in,
                              void* d_out, int out_size) {
    const float* x    = (const float*)d_in[0];
    const int*   ei   = (const int*)d_in[1];    // int32 (JAX x64 disabled)
    const float* attr = (const float*)d_in[2];
    const float* w1i  = (const float*)d_in[4];
    const float* w1   = (const float*)d_in[5];
    const float* w1r  = (const float*)d_in[6];
    const float* b1   = (const float*)d_in[7];
    const float* bg   = (const float*)d_in[8];
    const float* bb   = (const float*)d_in[9];
    const float* w2i  = (const float*)d_in[10];
    const float* w2   = (const float*)d_in[11];
    const float* w2r  = (const float*)d_in[12];
    const float* b2   = (const float*)d_in[13];
    float* out = (float*)d_out;

    int N = in_sizes[0];   // 100000
    int E = in_sizes[2];   // 3200000
    int nb = cdiv(N, SCAN_CHUNK);

    // ---- preprocessing: degrees, CSR grouped by target (attr payload) ----
    k_zero<<<cdiv(N, 256), 256>>>(N);
    k_pre<<<cdiv(E, 256), 256>>>(ei, attr, E, N);
    k_dinv_blocksum<<<nb, 256>>>(x, N);
    k_fillptr<<<nb, 256>>>(N, E);
    k_scatter<<<cdiv(E, 256), 256>>>(ei, attr, E, N);

    // ---- conv1 (K=3, H=16, L=4, relu) ----
    k_prop1i<<<cdiv(N, 8), 256>>>(w1i, w1, w1r, b1, N);   // norms + layer0 + z
    k_prop48<<<cdiv(N, 8), 256>>>(w1r, b1, w1, 1, N);
    k_prop48<<<cdiv(N, 8), 256>>>(w1r, b1, w1, 1, N);
    k_prop48<<<cdiv(N, 8), 256>>>(w1r, b1, w1, 0, N);

    // ---- batchnorm + relu, conv2 init ----
    k_bnstats<<<232, 256>>>(N);
    k_conv2init<<<cdiv(N, 256), 256>>>(bg, bb, w2i, w2r, b2, N);

    // ---- conv2 (K=3, C=1, L=4, no act) + mean + sigmoid ----
    k_prop3<<<cdiv(N, 8), 256>>>(0, 0, 0, w2, out, N);
    k_prop3<<<cdiv(N, 8), 256>>>(1, 1, 0, w2, out, N);
    k_prop3<<<cdiv(N, 8), 256>>>(0, 1, 0, w2, out, N);
    k_prop3<<<cdiv(N, 8), 256>>>(1, 1, 1, w2, out, N);
}

// round 10
// speedup vs baseline: 1.0367x; 1.0367x over previous
#include <cuda_runtime.h>
#include <cuda_fp16.h>
#include <math.h>

// Problem constants (fixed by the dataset)
#define N_MAX 100000
#define E_MAX 3200000
#define CH 48            // K*H = 3*16
#define ZSTRIDE 32       // half2 words per node (24 used + 8 pad = 128B line)
#define SCAN_CHUNK 1024
#define SCAN_NB ((N_MAX + SCAN_CHUNK - 1) / SCAN_CHUNK)   // 98

// ---------------- persistent device scratch ----------------
__device__ float2  g_xd[N_MAX];          // packed {x, dinv}
__device__ int     g_cnt[N_MAX];
__device__ int     g_colptr[N_MAX + 1];
__device__ int     g_epos[E_MAX];        // per-edge rank within its target bucket
__device__ int     g_bsum[SCAN_NB];
__device__ uint2   g_csr[E_MAX];         // {src, attr-bits} then {src, norm-bits}
__device__ __align__(16) __half2 g_z2[(size_t)N_MAX * ZSTRIDE]; // padded state
__device__ float   g_out[(size_t)N_MAX * CH]; // post-epilogue out (fp32)
__device__ float4  g_s[2][N_MAX];        // conv2 state ping/pong
__device__ float4  g_r2[N_MAX];          // conv2 root+bias per stack
__device__ float   g_bnsum[16];
__device__ float   g_bnsq[16];

// ---------------- preprocessing ----------------
__global__ void k_zero(int n) {
    int i = blockIdx.x * blockDim.x + threadIdx.x;
    if (i < n) g_cnt[i] = 0;
    if (i < 16) { g_bnsum[i] = 0.f; g_bnsq[i] = 0.f; }
}

// edge_index is int32. Only the cnt atomic; degree computed later from CSR.
__global__ void k_pre(const int* __restrict__ ei, int E, int n) {
    int e = blockIdx.x * blockDim.x + threadIdx.x;
    if (e >= E) return;
    int c = ei[E + e];
    c = min(max(c, 0), n - 1);
    g_epos[e] = atomicAdd(&g_cnt[c], 1);
}

// block sums of cnt for the hierarchical scan
__global__ void k_blocksum(int n) {
    __shared__ int sh[256];
    int base = blockIdx.x * SCAN_CHUNK;
    int tid = threadIdx.x;
    int s = 0;
    #pragma unroll
    for (int j = 0; j < 4; j++) {
        int i = base + tid * 4 + j;
        if (i < n) s += g_cnt[i];
    }
    sh[tid] = s;
    __syncthreads();
    for (int off = 128; off; off >>= 1) {
        if (tid < off) sh[tid] += sh[tid + off];
        __syncthreads();
    }
    if (tid == 0) g_bsum[blockIdx.x] = sh[0];
}

// fillptr with inline prefix of block sums
__global__ void k_fillptr(int n, int total) {
    __shared__ int sh[256];
    __shared__ int s_boff;
    int base = blockIdx.x * SCAN_CHUNK;
    int tid = threadIdx.x;
    if (tid < 32) {
        int acc = 0;
        for (int i = tid; i < blockIdx.x; i += 32) acc += g_bsum[i];
        #pragma unroll
        for (int o = 16; o; o >>= 1) acc += __shfl_xor_sync(0xffffffffu, acc, o);
        if (tid == 0) s_boff = acc;
    }
    int c[4];
    int s = 0;
    #pragma unroll
    for (int j = 0; j < 4; j++) {
        int i = base + tid * 4 + j;
        c[j] = (i < n) ? g_cnt[i] : 0;
        s += c[j];
    }
    sh[tid] = s;
    __syncthreads();
    for (int off = 1; off < 256; off <<= 1) {
        int v = (tid >= off) ? sh[tid - off] : 0;
        __syncthreads();
        sh[tid] += v;
        __syncthreads();
    }
    int run = s_boff + ((tid > 0) ? sh[tid - 1] : 0);
    #pragma unroll
    for (int j = 0; j < 4; j++) {
        int i = base + tid * 4 + j;
        if (i < n) { g_colptr[i] = run; run += c[j]; }
    }
    if (blockIdx.x == 0 && tid == 0) g_colptr[n] = total;
}

// scatter {src, attr}: no atomics (colptr + epos), no dinv gathers
__global__ void k_scatter(const int* __restrict__ ei, const float* __restrict__ attr, int E, int n) {
    int e = blockIdx.x * blockDim.x + threadIdx.x;
    if (e >= E) return;
    int r = ei[e];
    int c = ei[E + e];
    r = min(max(r, 0), n - 1);
    c = min(max(c, 0), n - 1);
    g_csr[g_colptr[c] + g_epos[e]] = make_uint2((unsigned)r, __float_as_uint(attr[e]));
}

// degree from CSR (coalesced), pack {x, dinv}  — warp per node
__global__ void k_deg(const float* __restrict__ x, int n) {
    int w = (blockIdx.x * blockDim.x + threadIdx.x) >> 5;
    int lane = threadIdx.x & 31;
    if (w >= n) return;
    int beg = g_colptr[w], end = g_colptr[w + 1];
    float d = 0.f;
    for (int i = beg + lane; i < end; i += 32)
        d += __uint_as_float(g_csr[i].y);
    #pragma unroll
    for (int o = 16; o; o >>= 1) d += __shfl_xor_sync(0xffffffffu, d, o);
    if (lane == 0) {
        float dv = (d > 0.f) ? rsqrtf(fmaxf(d, 1e-12f)) : 0.f;
        g_xd[w] = make_float2(x[w], dv);
    }
}

// ---------------- conv1 layer 0, fused ----------------
// per node: finalize norms in CSR, y = A_hat x, out1 = relu(y*wi + x*wr + b), z = out1 @ W
__global__ void k_prop1i(const float* __restrict__ wi, const float* __restrict__ W,
                         const float* __restrict__ wr, const float* __restrict__ b, int n) {
    __shared__ float s_wi[48], s_wr[48], s_b[48], s_W[768];
    int tid = threadIdx.x;
    if (tid < 48) { s_wi[tid] = wi[tid]; s_wr[tid] = wr[tid]; s_b[tid] = b[tid]; }
    for (int i = tid; i < 768; i += 256) s_W[i] = W[i];
    __syncthreads();

    int w = blockIdx.x * 8 + (tid >> 5);
    if (w >= n) return;
    int lane = tid & 31;
    float2 xdw = g_xd[w];
    float dinv_w = xdw.y, xv = xdw.x;
    int beg = g_colptr[w], end = g_colptr[w + 1];
    float acc = 0.f;
    for (int i = beg + lane; i < end; i += 32) {
        uint2 e = g_csr[i];
        float2 xd = g_xd[e.x];
        float nm = xd.y * __uint_as_float(e.y) * dinv_w;
        g_csr[i] = make_uint2(e.x, __float_as_uint(nm));
        acc += xd.x * nm;
    }
    #pragma unroll
    for (int o = 16; o; o >>= 1) acc += __shfl_xor_sync(0xffffffffu, acc, o);
    float yv = acc;   // all lanes have y

    if (lane < 24) {
        int k = lane >> 3;      // stack
        int j = lane & 7;       // half2 word within stack
        const float* wik = s_wi + k * 16;
        const float* wrk = s_wr + k * 16;
        const float* bk  = s_b  + k * 16;
        const float* Wk  = s_W  + k * 256;
        float z0 = 0.f, z1 = 0.f;
        #pragma unroll
        for (int hi = 0; hi < 16; hi++) {
            float o = fmaxf(yv * wik[hi] + xv * wrk[hi] + bk[hi], 0.f);
            z0 += o * Wk[hi * 16 + 2 * j];
            z1 += o * Wk[hi * 16 + 2 * j + 1];
        }
        g_z2[(size_t)w * ZSTRIDE + k * 8 + j] = __floats2half2_rn(z0, z1);
    } else {
        g_z2[(size_t)w * ZSTRIDE + lane] = __floats2half2_rn(0.f, 0.f);
    }
}

// hot kernel: out = relu(A_hat @ z + x*w_root + b); optionally fused z' = out @ W
// warp = 4 edge-slots x 8 chan-slots; 8-edge unroll + CSR software pipeline
__global__ void k_prop48(const float* __restrict__ wr, const float* __restrict__ b,
                         const float* __restrict__ W, int doTrans, int n) {
    __shared__ float s_out[8][CH];   // per-warp out vector
    __shared__ float s_W[768];       // 3 stacks x 16 x 16
    int tid = threadIdx.x;
    if (doTrans) {
        for (int i = tid; i < 768; i += 256) s_W[i] = W[i];
    }
    __syncthreads();

    int warpid = tid >> 5;
    int w = blockIdx.x * 8 + warpid;
    if (w >= n) return;
    int lane = tid & 31;
    int es = lane >> 3;    // edge slot 0..3
    int cs = lane & 7;     // chan slot 0..7 (0..5 carry real channels)
    int beg = g_colptr[w], end = g_colptr[w + 1];
    float accA[8] = {0.f, 0.f, 0.f, 0.f, 0.f, 0.f, 0.f, 0.f};
    float accB[8] = {0.f, 0.f, 0.f, 0.f, 0.f, 0.f, 0.f, 0.f};

    if (beg < end) {
        int last = end - 1;
        uint2 e0 = g_csr[min(beg + es, last)];
        uint2 e1 = g_csr[min(beg + es + 4, last)];
        bool ok0 = beg + es < end, ok1 = beg + es + 4 < end;
        for (int i = beg; i < end; i += 8) {
            int4 v0 = *((const int4*)(g_z2 + (size_t)e0.x * ZSTRIDE) + cs);
            int4 v1 = *((const int4*)(g_z2 + (size_t)e1.x * ZSTRIDE) + cs);
            float n0 = ok0 ? __uint_as_float(e0.y) : 0.f;
            float n1 = ok1 ? __uint_as_float(e1.y) : 0.f;
            int ni = i + 8;
            if (ni < end) {
                e0 = g_csr[min(ni + es, last)];
                e1 = g_csr[min(ni + es + 4, last)];
                ok0 = ni + es < end; ok1 = ni + es + 4 < end;
            }
            {
                float2 f0 = __half22float2(*(__half2*)&v0.x);
                float2 f1 = __half22float2(*(__half2*)&v0.y);
                float2 f2 = __half22float2(*(__half2*)&v0.z);
                float2 f3 = __half22float2(*(__half2*)&v0.w);
                accA[0] += f0.x * n0; accA[1] += f0.y * n0;
                accA[2] += f1.x * n0; accA[3] += f1.y * n0;
                accA[4] += f2.x * n0; accA[5] += f2.y * n0;
                accA[6] += f3.x * n0; accA[7] += f3.y * n0;
            }
            {
                float2 f0 = __half22float2(*(__half2*)&v1.x);
                float2 f1 = __half22float2(*(__half2*)&v1.y);
                float2 f2 = __half22float2(*(__half2*)&v1.z);
                float2 f3 = __half22float2(*(__half2*)&v1.w);
                accB[0] += f0.x * n1; accB[1] += f0.y * n1;
                accB[2] += f1.x * n1; accB[3] += f1.y * n1;
                accB[4] += f2.x * n1; accB[5] += f2.y * n1;
                accB[6] += f3.x * n1; accB[7] += f3.y * n1;
            }
        }
    }
    #pragma unroll
    for (int c = 0; c < 8; c++) {
        float a = accA[c] + accB[c];
        a += __shfl_xor_sync(0xffffffffu, a, 8);
        a += __shfl_xor_sync(0xffffffffu, a, 16);
        accA[c] = a;
    }
    if (es == 0 && cs < 6) {
        float xv = g_xd[w].x;
        int c0 = cs * 8;
        float o[8];
        #pragma unroll
        for (int c = 0; c < 8; c++) {
            o[c] = fmaxf(accA[c] + xv * wr[c0 + c] + b[c0 + c], 0.f);
            s_out[warpid][c0 + c] = o[c];
        }
        float4* op = (float4*)(g_out + (size_t)w * CH + c0);
        op[0] = make_float4(o[0], o[1], o[2], o[3]);
        op[1] = make_float4(o[4], o[5], o[6], o[7]);
    }
    if (doTrans) {
        __syncwarp();
        if (lane < 24) {
            int k = lane >> 3;
            int j = lane & 7;
            const float* ov = s_out[warpid] + k * 16;
            const float* Wk = s_W + k * 256;
            float z0 = 0.f, z1 = 0.f;
            #pragma unroll
            for (int hi = 0; hi < 16; hi++) {
                z0 += ov[hi] * Wk[hi * 16 + 2 * j];
                z1 += ov[hi] * Wk[hi * 16 + 2 * j + 1];
            }
            g_z2[(size_t)w * ZSTRIDE + k * 8 + j] = __floats2half2_rn(z0, z1);
        } else {
            g_z2[(size_t)w * ZSTRIDE + lane] = __floats2half2_rn(0.f, 0.f);
        }
    }
}

// ---------------- batchnorm + conv2 ----------------
__global__ void k_bnstats(int n) {
    int tid = blockIdx.x * blockDim.x + threadIdx.x;
    int stride = gridDim.x * blockDim.x;
    float s = 0.f, q = 0.f;
    for (int base = tid; base < n * 16; base += stride) {
        int node = base >> 4;
        int c = base & 15;
        const float* op = g_out + (size_t)node * CH;
        float h = (op[c] + op[16 + c] + op[32 + c]) * (1.f / 3.f);
        s += h; q += h * h;
    }
    atomicAdd(&g_bnsum[tid & 15], s);
    atomicAdd(&g_bnsq[tid & 15], q);
}

__global__ void k_conv2init(const float* __restrict__ bg, const float* __restrict__ bb,
                            const float* __restrict__ w2i, const float* __restrict__ w2r,
                            const float* __restrict__ b2, int n) {
    int node = blockIdx.x * blockDim.x + threadIdx.x;
    if (node >= n) return;
    const float* op = g_out + (size_t)node * CH;
    float invN = 1.f / (float)n;
    float s0 = 0.f, s1 = 0.f, s2 = 0.f;
    float r0 = b2[0], r1 = b2[1], r2 = b2[2];
    #pragma unroll
    for (int c = 0; c < 16; c++) {
        float h = (op[c] + op[16 + c] + op[32 + c]) * (1.f / 3.f);
        float mu = g_bnsum[c] * invN;
        float var = g_bnsq[c] * invN - mu * mu;
        float hb = (h - mu) * rsqrtf(var + 1e-5f) * bg[c] + bb[c];
        hb = fmaxf(hb, 0.f);
        s0 += hb * w2i[c];
        s1 += hb * w2i[16 + c];
        s2 += hb * w2i[32 + c];
        r0 += hb * w2r[c];
        r1 += hb * w2r[16 + c];
        r2 += hb * w2r[32 + c];
    }
    g_s[0][node] = make_float4(s0, s1, s2, 0.f);
    g_r2[node] = make_float4(r0, r1, r2, 0.f);
}

__global__ void k_prop3(int srcIdx, int useW, int finalOut,
                        const float* __restrict__ w2, float* __restrict__ dout, int n) {
    int w = (blockIdx.x * blockDim.x + threadIdx.x) >> 5;
    int lane = threadIdx.x & 31;
    if (w >= n) return;
    const float4* s = g_s[srcIdx];
    int beg = g_colptr[w], end = g_colptr[w + 1];
    float a0 = 0.f, a1 = 0.f, a2 = 0.f;
    for (int i = beg + lane; i < end; i += 32) {
        uint2 e = g_csr[i];
        float nm = __uint_as_float(e.y);
        float4 v = s[e.x];
        a0 += v.x * nm; a1 += v.y * nm; a2 += v.z * nm;
    }
    #pragma unroll
    for (int o = 16; o; o >>= 1) {
        a0 += __shfl_xor_sync(0xffffffffu, a0, o);
        a1 += __shfl_xor_sync(0xffffffffu, a1, o);
        a2 += __shfl_xor_sync(0xffffffffu, a2, o);
    }
    if (lane == 0) {
        if (useW) { a0 *= w2[0]; a1 *= w2[1]; a2 *= w2[2]; }
        float4 r = g_r2[w];
        a0 += r.x; a1 += r.y; a2 += r.z;
        if (finalOut) {
            float m = (a0 + a1 + a2) * (1.f / 3.f);
            dout[w] = 1.f / (1.f + expf(-m));
        } else {
            g_s[1 - srcIdx][w] = make_float4(a0, a1, a2, 0.f);
        }
    }
}

static inline int cdiv(int a, int b) { return (a + b - 1) / b; }

extern "C" void kernel_launch(void* const* d_in, const int* in_sizes, int n_in,
                              void* d_out, int out_size) {
    const float* x    = (const float*)d_in[0];
    const int*   ei   = (const int*)d_in[1];    // int32 (JAX x64 disabled)
    const float* attr = (const float*)d_in[2];
    const float* w1i  = (const float*)d_in[4];
    const float* w1   = (const float*)d_in[5];
    const float* w1r  = (const float*)d_in[6];
    const float* b1   = (const float*)d_in[7];
    const float* bg   = (const float*)d_in[8];
    const float* bb   = (const float*)d_in[9];
    const float* w2i  = (const float*)d_in[10];
    const float* w2   = (const float*)d_in[11];
    const float* w2r  = (const float*)d_in[12];
    const float* b2   = (const float*)d_in[13];
    float* out = (float*)d_out;

    int N = in_sizes[0];   // 100000
    int E = in_sizes[2];   // 3200000
    int nb = cdiv(N, SCAN_CHUNK);

    // ---- preprocessing: counts, CSR grouped by target, degrees from CSR ----
    k_zero<<<cdiv(N, 256), 256>>>(N);
    k_pre<<<cdiv(E, 256), 256>>>(ei, E, N);
    k_blocksum<<<nb, 256>>>(N);
    k_fillptr<<<nb, 256>>>(N, E);
    k_scatter<<<cdiv(E, 256), 256>>>(ei, attr, E, N);
    k_deg<<<cdiv(N, 8), 256>>>(x, N);

    // ---- conv1 (K=3, H=16, L=4, relu) ----
    k_prop1i<<<cdiv(N, 8), 256>>>(w1i, w1, w1r, b1, N);   // norms + layer0 + z
    k_prop48<<<cdiv(N, 8), 256>>>(w1r, b1, w1, 1, N);
    k_prop48<<<cdiv(N, 8), 256>>>(w1r, b1, w1, 1, N);
    k_prop48<<<cdiv(N, 8), 256>>>(w1r, b1, w1, 0, N);

    // ---- batchnorm + relu, conv2 init ----
    k_bnstats<<<232, 256>>>(N);
    k_conv2init<<<cdiv(N, 256), 256>>>(bg, bb, w2i, w2r, b2, N);

    // ---- conv2 (K=3, C=1, L=4, no act) + mean + sigmoid ----
    k_prop3<<<cdiv(N, 8), 256>>>(0, 0, 0, w2, out, N);
    k_prop3<<<cdiv(N, 8), 256>>>(1, 1, 0, w2, out, N);
    k_prop3<<<cdiv(N, 8), 256>>>(0, 1, 0, w2, out, N);
    k_prop3<<<cdiv(N, 8), 256>>>(1, 1, 1, w2, out, N);
}